// round 11
// baseline (speedup 1.0000x reference)
#include <cuda_runtime.h>

// SSIM loss — R11: 320 threads (single-round phases), 8-col H-tasks with
// compressed A-field results, two-field algebra, ticket-fused finish.

typedef unsigned long long u64;

#define TX 64
#define TY 32
#define HALO 5
#define INW 74                      // TX + 2*HALO
#define VS 75                       // u64 stride (odd -> conflict-free LDS.64)
#define NTHREADS 320
#define IMG 512
#define TILES_X 8
#define TILES_Y 16
#define PLANES 48
#define NBLOCKS (PLANES * TILES_Y * TILES_X)   // 6144
#define NPIX 12582912.0f

#define C1 1.0e-4f
#define C2 9.0e-4f

#define N_V (TY * VS)               // 2400 u64 per buffer

__device__ float g_partials[NBLOCKS];
__device__ unsigned g_ticket = 0;

// Normalized 1D Gaussian, window=11, sigma=1.5
__device__ __forceinline__ constexpr float Wt(int k) {
    constexpr float w[11] = {
        0.00102838f, 0.00759877f, 0.03600081f, 0.10936072f, 0.21300553f,
        0.26601169f,
        0.21300553f, 0.10936072f, 0.03600081f, 0.00759877f, 0.00102838f
    };
    return w[k];
}

// ---- f32x2 packed helpers ----
__device__ __forceinline__ u64 pk(float lo, float hi) {
    u64 r; asm("mov.b64 %0, {%1, %2};" : "=l"(r) : "f"(lo), "f"(hi)); return r;
}
__device__ __forceinline__ float2 upk(u64 v) {
    float2 r; asm("mov.b64 {%0, %1}, %2;" : "=f"(r.x), "=f"(r.y) : "l"(v)); return r;
}
__device__ __forceinline__ u64 fma2(u64 a, u64 b, u64 c) {
    u64 d; asm("fma.rn.f32x2 %0, %1, %2, %3;" : "=l"(d) : "l"(a), "l"(b), "l"(c)); return d;
}
__device__ __forceinline__ u64 mul2(u64 a, u64 b) {
    u64 d; asm("mul.rn.f32x2 %0, %1, %2;" : "=l"(d) : "l"(a), "l"(b)); return d;
}
__device__ __forceinline__ u64 wsel(const u64 (&w)[6], int k) {
    return w[k < 6 ? k : 10 - k];
}

// Vertical-blur task: WIN input rows -> NOUT output rows for column c.
template<int WIN, int NOUT>
__device__ __forceinline__ void vtask(
    const float* __restrict__ p_plane, const float* __restrict__ t_plane,
    bool interior, int gx, int gybase,
    u64* __restrict__ s_VA, u64* __restrict__ s_VB,
    int y0, int c, const u64 (&w2)[6])
{
    u64 a[WIN];
    if (interior) {
        const float* pp = p_plane + (long)gybase * IMG + gx;
        const float* tp = t_plane + (long)gybase * IMG + gx;
        #pragma unroll
        for (int i = 0; i < WIN; i++)
            a[i] = pk(__ldg(pp + i * IMG), __ldg(tp + i * IMG));
    } else {
        const bool xok = (unsigned)gx < IMG;
        #pragma unroll
        for (int i = 0; i < WIN; i++) {
            int gy = gybase + i;
            float pv = 0.0f, tv = 0.0f;
            if (xok & ((unsigned)gy < IMG)) {
                long o = (long)gy * IMG + gx;
                pv = __ldg(p_plane + o);
                tv = __ldg(t_plane + o);
            }
            a[i] = pk(pv, tv);
        }
    }
    #pragma unroll
    for (int j = 0; j < NOUT; j++) {
        u64 acc = mul2(wsel(w2, 0), a[j]);
        #pragma unroll
        for (int k = 1; k < 11; k++) acc = fma2(wsel(w2, k), a[j + k], acc);
        s_VA[(y0 + j) * VS + c] = acc;
    }
    #pragma unroll
    for (int i = 0; i < WIN; i++) {     // (p,t) -> (p^2+t^2, p*t)
        float2 v = upk(a[i]);
        a[i] = pk(fmaf(v.x, v.x, v.y * v.y), v.x * v.y);
    }
    #pragma unroll
    for (int j = 0; j < NOUT; j++) {
        u64 acc = mul2(wsel(w2, 0), a[j]);
        #pragma unroll
        for (int k = 1; k < 11; k++) acc = fma2(wsel(w2, k), a[j + k], acc);
        s_VB[(y0 + j) * VS + c] = acc;
    }
}

__global__ __launch_bounds__(NTHREADS, 3)
void ssim_tile_kernel(const float* __restrict__ pred,
                      const float* __restrict__ targ,
                      float* __restrict__ out) {
    __shared__ u64 s_VA[N_V];     // V-blurred (mu_p, mu_t)
    __shared__ u64 s_VB[N_V];     // V-blurred (E[p^2]+E[t^2], E[pt])
    __shared__ float s_warp[10];
    __shared__ int   s_last;

    const int tid = threadIdx.x;
    const int ox = blockIdx.x * TX;
    const int oy = blockIdx.y * TY;
    const long plane_base = (long)blockIdx.z * (IMG * IMG);
    const float* __restrict__ p_plane = pred + plane_base;
    const float* __restrict__ t_plane = targ + plane_base;

    u64 w2[6];
    #pragma unroll
    for (int k = 0; k < 6; k++) w2[k] = pk(Wt(k), Wt(k));

    // ---- Phase 1: vertical blur from global, SINGLE round.
    // 296 tasks = 74 halo-cols x 4 row-groups of 8 outputs (window 18).
    const bool interior =
        (blockIdx.x != 0) & (blockIdx.x != TILES_X - 1) &
        (blockIdx.y != 0) & (blockIdx.y != TILES_Y - 1);

    if (tid < INW * 4) {
        int c = tid % INW;
        int g = tid / INW;
        int gx = ox + c - HALO;
        int y0 = 8 * g;
        vtask<18, 8>(p_plane, t_plane, interior, gx,
                     oy + y0 - HALO, s_VA, s_VB, y0, c, w2);
    }
    __syncthreads();

    // ---- Phase 2: horizontal blur + SSIM, SINGLE round.
    // 256 tasks of 8 columns (window 18). A-field results compressed to
    // (mu_pt, mu_p^2 + mu_t^2) so the A window dies before B loads.
    float local = 0.0f;
    if (tid < 256) {
        const int r = tid & 31;
        const int grp = tid >> 5;              // 0..7
        const int base = r * VS + 8 * grp;

        u64 m1[8];                              // (mu_pt, mu_p2+mu_t2)
        {
            u64 h[18];
            #pragma unroll
            for (int i = 0; i < 18; i++) h[i] = s_VA[base + i];
            #pragma unroll
            for (int j = 0; j < 8; j++) {
                u64 acc = mul2(wsel(w2, 0), h[j]);
                #pragma unroll
                for (int k = 1; k < 11; k++) acc = fma2(wsel(w2, k), h[j + k], acc);
                float2 mu = upk(acc);
                m1[j] = pk(mu.x * mu.y, fmaf(mu.x, mu.x, mu.y * mu.y));
            }
        }
        {
            u64 h[18];
            #pragma unroll
            for (int i = 0; i < 18; i++) h[i] = s_VB[base + i];
            #pragma unroll
            for (int j = 0; j < 8; j++) {
                u64 acc = mul2(wsel(w2, 0), h[j]);
                #pragma unroll
                for (int k = 1; k < 11; k++) acc = fma2(wsel(w2, k), h[j + k], acc);
                float2 sb = upk(acc);           // (E[p^2]+E[t^2], E[pt])
                float2 m = upk(m1[j]);          // (mu_pt, mu_p2+mu_t2)
                float num = (2.0f * m.x + C1) * (2.0f * (sb.y - m.x) + C2);
                float den = (m.y + C1) * ((sb.x - m.y) + C2);
                local += __fdividef(num, den);
            }
        }
    }

    // ---- Phase 3: block reduction (10 warps) ----
    float v = local;
    #pragma unroll
    for (int off = 16; off; off >>= 1)
        v += __shfl_xor_sync(0xFFFFFFFFu, v, off);
    if ((tid & 31) == 0) s_warp[tid >> 5] = v;
    __syncthreads();
    if (tid < 16) {
        v = (tid < 10) ? s_warp[tid] : 0.0f;
        #pragma unroll
        for (int off = 8; off; off >>= 1)
            v += __shfl_xor_sync(0x0000FFFFu, v, off);
    }
    if (tid == 0) {
        int bl = (blockIdx.z * TILES_Y + blockIdx.y) * TILES_X + blockIdx.x;
        g_partials[bl] = v;
        __threadfence();
        unsigned t = atomicInc(&g_ticket, NBLOCKS - 1);  // wraps -> self-reset
        s_last = (t == NBLOCKS - 1);
    }
    __syncthreads();

    // ---- Phase 4: last block folds partials (fixed order, deterministic) ----
    if (s_last) {
        float s = 0.0f;
        for (int i = tid; i < NBLOCKS; i += NTHREADS)
            s += __ldcg(&g_partials[i]);
        #pragma unroll
        for (int off = 16; off; off >>= 1)
            s += __shfl_xor_sync(0xFFFFFFFFu, s, off);
        if ((tid & 31) == 0) s_warp[tid >> 5] = s;
        __syncthreads();
        if (tid < 16) {
            s = (tid < 10) ? s_warp[tid] : 0.0f;
            #pragma unroll
            for (int off = 8; off; off >>= 1)
                s += __shfl_xor_sync(0x0000FFFFu, s, off);
            if (tid == 0) out[0] = 1.0f - s * (1.0f / NPIX);
        }
    }
}

extern "C" void kernel_launch(void* const* d_in, const int* in_sizes, int n_in,
                              void* d_out, int out_size) {
    const float* pred = (const float*)d_in[0];
    const float* targ = (const float*)d_in[1];
    float* out = (float*)d_out;

    dim3 grid(TILES_X, TILES_Y, PLANES);
    ssim_tile_kernel<<<grid, NTHREADS>>>(pred, targ, out);
}